// round 2
// baseline (speedup 1.0000x reference)
#include <cuda_runtime.h>
#include <cstdint>

// ---------------------------------------------------------------------------
// Problem constants
// ---------------------------------------------------------------------------
#define BATCH   1568
#define NTOK    64
#define CDIM    512
#define HEADS   16
#define HD      32
#define NW      49
#define MTOT    (BATCH * NTOK)          // 100352
#define QKVN    (3 * CDIM)              // 1536

// ---------------------------------------------------------------------------
// Device scratch (static globals: allocation-free per harness rules)
// ---------------------------------------------------------------------------
__device__ float g_qkv[(size_t)MTOT * QKVN];    // 616 MB: qkv projection output
__device__ float g_att[(size_t)MTOT * CDIM];    // 205 MB: attention output (B,N,C)
__device__ float g_bias[HEADS * NTOK * NTOK];   // (16,64,64) CRPB bias
__device__ float g_tbl[225 * HEADS];            // CRPB table (2W-1)^2 x H
__device__ float g_scale[HEADS];                // clamped temperature per head

// ---------------------------------------------------------------------------
// Kernel 1a: CRPB MLP table + temperature scale
// 225 entries; each thread does 384-hidden MLP -> 16 outputs.
// ---------------------------------------------------------------------------
__global__ void crpb_tbl_kernel(const float* __restrict__ ct,
                                const float* __restrict__ w1,
                                const float* __restrict__ b1,
                                const float* __restrict__ w2,
                                const float* __restrict__ ts)
{
    int e = threadIdx.x;
    if (e < HEADS) {
        // exp(min(t_scale, ln(100)))
        g_scale[e] = expf(fminf(ts[e], 4.6051701859880913680f));
    }
    if (e < 225) {
        float c0 = ct[e * 2 + 0];
        float c1 = ct[e * 2 + 1];
        float acc[HEADS];
#pragma unroll
        for (int h = 0; h < HEADS; h++) acc[h] = 0.f;
        for (int j = 0; j < 384; j++) {
            float hv = fmaxf(w1[j * 2 + 0] * c0 + w1[j * 2 + 1] * c1 + b1[j], 0.f);
#pragma unroll
            for (int h = 0; h < HEADS; h++) acc[h] += w2[h * 384 + j] * hv;
        }
#pragma unroll
        for (int h = 0; h < HEADS; h++) g_tbl[e * HEADS + h] = acc[h];
    }
}

// ---------------------------------------------------------------------------
// Kernel 1b: bias[h][i][j] = 16*sigmoid(tbl[rel_index[i][j]][h])
// ---------------------------------------------------------------------------
__global__ void bias_fill_kernel(const int* __restrict__ ridx)
{
    int t = blockIdx.x * blockDim.x + threadIdx.x;
    if (t >= HEADS * NTOK * NTOK) return;
    int h  = t >> 12;          // / 4096
    int ij = t & 4095;
    float v = g_tbl[ridx[ij] * HEADS + h];
    g_bias[t] = 16.f / (1.f + __expf(-v));
}

// ---------------------------------------------------------------------------
// Kernel 2/4: tiled fp32 GEMM  C[m][n] = sum_k A[m][k]*B[n][k] + bias[n]
// A: MxK row-major, B: NxK row-major (i.e. C = A @ B^T).
// 128x128 block tile, K-tile 16, 256 threads, 8x8 per thread.
// M % 128 == 0, N % 128 == 0, K % 16 == 0 (true for all our shapes).
// ---------------------------------------------------------------------------
#define BM 128
#define BN 128
#define BK 16

__global__ __launch_bounds__(256, 2)
void gemm_abT_kernel(const float* __restrict__ A, const float* __restrict__ B,
                     const float* __restrict__ bias, float* __restrict__ C,
                     int M, int N, int K)
{
    __shared__ float As[BK][BM + 4];
    __shared__ float Bs[BK][BN + 4];

    const int bm  = blockIdx.y * BM;
    const int bn  = blockIdx.x * BN;
    const int tid = threadIdx.x;
    const int tx  = tid & 15;
    const int ty  = tid >> 4;

    float acc[8][8];
#pragma unroll
    for (int i = 0; i < 8; i++)
#pragma unroll
        for (int j = 0; j < 8; j++) acc[i][j] = 0.f;

    for (int k0 = 0; k0 < K; k0 += BK) {
#pragma unroll
        for (int l = 0; l < 2; l++) {
            int f   = tid + l * 256;     // 0..511
            int row = f >> 2;            // 0..127
            int kv  = (f & 3) * 4;       // 0,4,8,12
            float4 va = *(const float4*)(A + (size_t)(bm + row) * K + k0 + kv);
            As[kv + 0][row] = va.x; As[kv + 1][row] = va.y;
            As[kv + 2][row] = va.z; As[kv + 3][row] = va.w;
            float4 vb = *(const float4*)(B + (size_t)(bn + row) * K + k0 + kv);
            Bs[kv + 0][row] = vb.x; Bs[kv + 1][row] = vb.y;
            Bs[kv + 2][row] = vb.z; Bs[kv + 3][row] = vb.w;
        }
        __syncthreads();

#pragma unroll
        for (int kk = 0; kk < BK; kk++) {
            float a[8], b[8];
#pragma unroll
            for (int i = 0; i < 8; i++) a[i] = As[kk][ty * 8 + i];
#pragma unroll
            for (int j = 0; j < 8; j++) b[j] = Bs[kk][tx * 8 + j];
#pragma unroll
            for (int i = 0; i < 8; i++)
#pragma unroll
                for (int j = 0; j < 8; j++) acc[i][j] += a[i] * b[j];
        }
        __syncthreads();
    }

#pragma unroll
    for (int i = 0; i < 8; i++) {
        int m = bm + ty * 8 + i;
#pragma unroll
        for (int j = 0; j < 8; j += 4) {
            int n = bn + tx * 8 + j;
            float4 o;
            o.x = acc[i][j + 0] + bias[n + 0];
            o.y = acc[i][j + 1] + bias[n + 1];
            o.z = acc[i][j + 2] + bias[n + 2];
            o.w = acc[i][j + 3] + bias[n + 3];
            *(float4*)(C + (size_t)m * N + n) = o;
        }
    }
}

// ---------------------------------------------------------------------------
// Kernel 3: attention. One block per (window b, head h).
// Loads Q/K/V 64x32 from g_qkv, cosine-normalizes Q,K rows, computes
// S = scale*Qn Kn^T + bias[h] + mask[b%49], row softmax, O = S V,
// writes O to g_att in (B, N, C) layout at column h*32.
// ---------------------------------------------------------------------------
__global__ __launch_bounds__(256, 4)
void attn_kernel(const float* __restrict__ mask, float* __restrict__ out)
{
    const int bh = blockIdx.x;
    const int b  = bh >> 4;          // / HEADS
    const int h  = bh & 15;
    const int w  = b % NW;

    __shared__ float Qs[64][33];
    __shared__ float Ks[64][33];
    __shared__ float Vs[64][33];
    __shared__ float Ss[64][65];

    const int tid = threadIdx.x;
    const float* base = g_qkv + (size_t)b * NTOK * QKVN + h * HD;

    // load Q, K, V tiles (float4 over head dim)
#pragma unroll
    for (int l = 0; l < 2; l++) {
        int f = tid + l * 256;       // 0..511
        int t = f >> 3;              // token 0..63
        int d = (f & 7) * 4;         // 0..28
        const float* rp = base + (size_t)t * QKVN;
        float4 q4 = *(const float4*)(rp + 0 * CDIM + d);
        float4 k4 = *(const float4*)(rp + 1 * CDIM + d);
        float4 v4 = *(const float4*)(rp + 2 * CDIM + d);
        Qs[t][d + 0] = q4.x; Qs[t][d + 1] = q4.y; Qs[t][d + 2] = q4.z; Qs[t][d + 3] = q4.w;
        Ks[t][d + 0] = k4.x; Ks[t][d + 1] = k4.y; Ks[t][d + 2] = k4.z; Ks[t][d + 3] = k4.w;
        Vs[t][d + 0] = v4.x; Vs[t][d + 1] = v4.y; Vs[t][d + 2] = v4.z; Vs[t][d + 3] = v4.w;
    }
    __syncthreads();

    // cosine normalization of Q and K rows (eps = 1e-12 on the norm)
    if (tid < 128) {
        float* row = (tid < 64) ? Qs[tid] : Ks[tid - 64];
        float s = 0.f;
#pragma unroll
        for (int d = 0; d < HD; d++) s += row[d] * row[d];
        float inv = 1.0f / fmaxf(sqrtf(s), 1e-12f);
#pragma unroll
        for (int d = 0; d < HD; d++) row[d] *= inv;
    }
    __syncthreads();

    // S = scale * Qn Kn^T + bias + mask ; 4x4 register tile per thread
    {
        const int tx = tid & 15;
        const int ty = tid >> 4;
        const float sc = g_scale[h];
        const float* bi = g_bias + h * NTOK * NTOK;
        const float* mk = mask + (size_t)w * NTOK * NTOK;
        float s4[4][4];
#pragma unroll
        for (int i = 0; i < 4; i++)
#pragma unroll
            for (int j = 0; j < 4; j++) s4[i][j] = 0.f;
#pragma unroll
        for (int d = 0; d < HD; d++) {
            float qa[4], kb[4];
#pragma unroll
            for (int i = 0; i < 4; i++) qa[i] = Qs[ty * 4 + i][d];
#pragma unroll
            for (int j = 0; j < 4; j++) kb[j] = Ks[tx * 4 + j][d];
#pragma unroll
            for (int i = 0; i < 4; i++)
#pragma unroll
                for (int j = 0; j < 4; j++) s4[i][j] += qa[i] * kb[j];
        }
#pragma unroll
        for (int i = 0; i < 4; i++) {
            int r = ty * 4 + i;
#pragma unroll
            for (int j = 0; j < 4; j++) {
                int c = tx * 4 + j;
                Ss[r][c] = s4[i][j] * sc + bi[r * 64 + c] + mk[r * 64 + c];
            }
        }
    }
    __syncthreads();

    // row softmax: 8 warps x 8 rows, 2 cols per lane
    {
        const int wid  = tid >> 5;
        const int lane = tid & 31;
        for (int r = wid * 8; r < wid * 8 + 8; r++) {
            float v0 = Ss[r][lane];
            float v1 = Ss[r][lane + 32];
            float m = fmaxf(v0, v1);
#pragma unroll
            for (int off = 16; off > 0; off >>= 1)
                m = fmaxf(m, __shfl_xor_sync(0xffffffffu, m, off));
            float e0 = __expf(v0 - m);
            float e1 = __expf(v1 - m);
            float s = e0 + e1;
#pragma unroll
            for (int off = 16; off > 0; off >>= 1)
                s += __shfl_xor_sync(0xffffffffu, s, off);
            float inv = 1.0f / s;
            Ss[r][lane]      = e0 * inv;
            Ss[r][lane + 32] = e1 * inv;
        }
    }
    __syncthreads();

    // O = P V : thread computes 4 rows x 2 cols
    {
        const int tx = tid & 15;
        const int ty = tid >> 4;
        float o[4][2];
#pragma unroll
        for (int i = 0; i < 4; i++) { o[i][0] = 0.f; o[i][1] = 0.f; }
#pragma unroll 8
        for (int j = 0; j < 64; j++) {
            float v0 = Vs[j][tx * 2 + 0];
            float v1 = Vs[j][tx * 2 + 1];
#pragma unroll
            for (int i = 0; i < 4; i++) {
                float p = Ss[ty * 4 + i][j];
                o[i][0] += p * v0;
                o[i][1] += p * v1;
            }
        }
#pragma unroll
        for (int i = 0; i < 4; i++) {
            int t = ty * 4 + i;
            float* op = out + (size_t)(b * NTOK + t) * CDIM + h * HD + tx * 2;
            op[0] = o[i][0];
            op[1] = o[i][1];
        }
    }
}

// ---------------------------------------------------------------------------
// Launch
// ---------------------------------------------------------------------------
extern "C" void kernel_launch(void* const* d_in, const int* in_sizes, int n_in,
                              void* d_out, int out_size)
{
    const float* x        = (const float*)d_in[0];
    const float* mask     = (const float*)d_in[1];
    const float* qkv_w    = (const float*)d_in[2];
    const float* qkv_b    = (const float*)d_in[3];
    const float* proj_w   = (const float*)d_in[4];
    const float* proj_b   = (const float*)d_in[5];
    const float* t_scale  = (const float*)d_in[6];
    const float* crpb_w1  = (const float*)d_in[7];
    const float* crpb_b1  = (const float*)d_in[8];
    const float* crpb_w2  = (const float*)d_in[9];
    const float* ctable   = (const float*)d_in[10];
    const int*   rel_idx  = (const int*)d_in[11];
    float*       out      = (float*)d_out;

    float* qkv = nullptr;
    float* att = nullptr;
    cudaGetSymbolAddress((void**)&qkv, g_qkv);
    cudaGetSymbolAddress((void**)&att, g_att);

    // 1. CRPB table + scale, bias fill
    crpb_tbl_kernel<<<1, 256>>>(ctable, crpb_w1, crpb_b1, crpb_w2, t_scale);
    bias_fill_kernel<<<(HEADS * NTOK * NTOK + 255) / 256, 256>>>(rel_idx);

    // 2. QKV projection: (100352 x 512) @ (1536 x 512)^T -> (100352 x 1536)
    {
        dim3 grid(QKVN / BN, MTOT / BM);
        gemm_abT_kernel<<<grid, 256>>>(x, qkv_w, qkv_b, qkv, MTOT, QKVN, CDIM);
    }

    // 3. attention: one block per (window, head)
    attn_kernel<<<BATCH * HEADS, 256>>>(mask, att);

    // 4. output projection: (100352 x 512) @ (512 x 512)^T -> d_out
    {
        dim3 grid(CDIM / BN, MTOT / BM);
        gemm_abT_kernel<<<grid, 256>>>(att, proj_w, proj_b, out, MTOT, CDIM, CDIM);
    }
}